// round 7
// baseline (speedup 1.0000x reference)
#include <cuda_runtime.h>
#include <cstdint>
#include <math.h>

#define N_  32
#define T_  1024
#define D_  512
#define H_  512
#define G4  2048

#define NB   128
#define NTH  576    // 16 GEMM warps + 2 reduce warps
#define APW  288    // partial plane stride (ull), index np*18+c

typedef unsigned long long ull;

__device__ __forceinline__ void fma2(ull& d, const ull a, const ull b) {
    asm("fma.rn.f32x2 %0, %1, %2, %0;" : "+l"(d) : "l"(a), "l"(b));
}
__device__ __forceinline__ void add2(ull& d, const ull a) {
    asm("add.rn.f32x2 %0, %0, %1;" : "+l"(d) : "l"(a));
}
__device__ __forceinline__ ull bcast2(float x) {
    ull r; asm("mov.b64 %0, {%1, %1};" : "=l"(r) : "f"(x)); return r;
}
__device__ __forceinline__ void unpack2(float& lo, float& hi, ull a) {
    asm("mov.b64 {%0, %1}, %2;" : "=f"(lo), "=f"(hi) : "l"(a));
}
__device__ __forceinline__ float fsig(float x) { return 1.f / (1.f + __expf(-x)); }
__device__ __forceinline__ float ftanh(float x) { return 2.f / (1.f + __expf(-2.f * x)) - 1.f; }

// ---------------- device scratch -------------------------------------------------
__device__ float g_xw[(size_t)N_ * T_ * G4];   // x@Wx + b, [n][t][2048]
__device__ float g_hbuf[2][H_][N_];            // double-buffered h, [k][n]
__device__ unsigned int g_flag[NB];            // flag[b] = v  <=>  h(v-1) published by CTA b

// ---------------- init kernel: flags = 1, h0 -> g_hbuf[0] -------------------------
__global__ void init_state_kernel(const float* __restrict__ h0)
{
    int i = blockIdx.x * blockDim.x + threadIdx.x;
    if (i < NB) g_flag[i] = 1u;
    if (i < H_ * N_) {
        int j = i >> 5, n = i & 31;
        g_hbuf[0][j][n] = h0[(size_t)n * H_ + j];
    }
}

// ---------------- Phase 1: xw = x @ Wx + b (unchanged, proven) --------------------
__global__ __launch_bounds__(256, 2) void gemm_xw_kernel(const float* __restrict__ x,
                                                         const float* __restrict__ Wx,
                                                         const float* __restrict__ bias)
{
    __shared__ float As[8][128];
    __shared__ float Bs[8][128];
    const int tid = threadIdx.x;
    const int bm = blockIdx.y, bn = blockIdx.x;
    const int tx = tid & 15, ty = tid >> 4;
    const int a_row = tid >> 1, a_k = (tid & 1) << 2;
    const int b_row = tid >> 5, b_col = (tid & 31) << 2;

    const float* xA = x + (size_t)(bm * 128 + a_row) * D_ + a_k;
    const float* wB = Wx + (size_t)b_row * G4 + bn * 128 + b_col;

    ull accp[8][4];
#pragma unroll
    for (int i = 0; i < 8; i++)
#pragma unroll
        for (int j = 0; j < 4; j++) accp[i][j] = 0ULL;

    for (int k0 = 0; k0 < D_; k0 += 8) {
        float4 av = *(const float4*)(xA + k0);
        float4 bv = *(const float4*)(wB + (size_t)k0 * G4);
        __syncthreads();
        As[a_k + 0][a_row] = av.x;
        As[a_k + 1][a_row] = av.y;
        As[a_k + 2][a_row] = av.z;
        As[a_k + 3][a_row] = av.w;
        *(float4*)&Bs[b_row][b_col] = bv;
        __syncthreads();
#pragma unroll
        for (int kk = 0; kk < 8; kk++) {
            float a0[8];
            *(float4*)(a0)     = *(const float4*)&As[kk][ty * 8];
            *(float4*)(a0 + 4) = *(const float4*)&As[kk][ty * 8 + 4];
            ulonglong2 q0 = *(const ulonglong2*)&Bs[kk][tx * 8];
            ulonglong2 q1 = *(const ulonglong2*)&Bs[kk][tx * 8 + 4];
            ull b2[4] = {q0.x, q0.y, q1.x, q1.y};
            ull a2[8];
#pragma unroll
            for (int i = 0; i < 8; i++) a2[i] = bcast2(a0[i]);
#pragma unroll
            for (int i = 0; i < 8; i++)
#pragma unroll
                for (int j = 0; j < 4; j++)
                    fma2(accp[i][j], a2[i], b2[j]);
        }
    }

    ulonglong2 bq0 = *(const ulonglong2*)(bias + bn * 128 + tx * 8);
    ulonglong2 bq1 = *(const ulonglong2*)(bias + bn * 128 + tx * 8 + 4);
    ull bb2[4] = {bq0.x, bq0.y, bq1.x, bq1.y};
#pragma unroll
    for (int i = 0; i < 8; i++) {
#pragma unroll
        for (int j = 0; j < 4; j++) add2(accp[i][j], bb2[j]);
        size_t row = (size_t)(bm * 128 + ty * 8 + i);
        ulonglong2 s0, s1;
        s0.x = accp[i][0]; s0.y = accp[i][1];
        s1.x = accp[i][2]; s1.y = accp[i][3];
        *(ulonglong2*)(g_xw + row * G4 + bn * 128 + tx * 8)     = s0;
        *(ulonglong2*)(g_xw + row * G4 + bn * 128 + tx * 8 + 4) = s1;
    }
}

// ---------------- Phase 2: dataflow persistent kernel -----------------------------
extern __shared__ float smem_dyn[];

__global__ __launch_bounds__(NTH, 1) void lstm_rec_kernel(const float* __restrict__ Wh,
                                                          float* __restrict__ out)
{
    // smem: ws[512][16] | ap ull[2][16][APW]
    float* ws = smem_dyn;                       // 8192 floats (32KB)
    ull*   ap = (ull*)(ws + 512 * 16);          // 2*16*APW ull (72KB)

    const int b   = blockIdx.x;
    const int tid = threadIdx.x;
    const int j0  = b * 4;

    // weights: ws[k][c], c = gate*4+jj
    for (int idx = tid; idx < 512 * 16; idx += NTH) {
        int k = idx >> 4, c = idx & 15;
        ws[idx] = Wh[(size_t)k * G4 + (c >> 2) * H_ + j0 + (c & 3)];
    }
    __syncthreads();

    if (tid < 512) {
        // ================= GEMM worker warps =================
        const int w    = tid >> 5;
        const int lane = tid & 31;
        const int kg   = lane >> 4;
        const int pos  = lane & 15;
        const int n0   = (pos & 3) * 8;
        const int cg4  = (pos >> 2) * 4;
        const int kbase = w * 32 + kg * 16;
        const unsigned* fp = &g_flag[w * 8 + (lane & 7)];

        for (int t = 0; t < T_; t++) {
            // wait for my 8 producers to publish h(t)
            unsigned target = (unsigned)t + 1u, v;
            do {
                asm volatile("ld.acquire.gpu.global.u32 %0, [%1];" : "=r"(v) : "l"(fp));
            } while (__any_sync(0xFFFFFFFFu, v < target));

            const float* hb = &g_hbuf[t & 1][0][0];
            ull acc[4][4];
#pragma unroll
            for (int u = 0; u < 4; u++)
#pragma unroll
                for (int c = 0; c < 4; c++) acc[u][c] = 0ULL;

#pragma unroll
            for (int i = 0; i < 16; i++) {
                int k = kbase + i;
                ulonglong2 hA = __ldcg((const ulonglong2*)(hb + k * 32 + n0));
                ulonglong2 hB = __ldcg((const ulonglong2*)(hb + k * 32 + n0 + 4));
                ull hv[4] = {hA.x, hA.y, hB.x, hB.y};
                float4 wf = *(const float4*)(ws + k * 16 + cg4);
                ull wb[4] = {bcast2(wf.x), bcast2(wf.y), bcast2(wf.z), bcast2(wf.w)};
#pragma unroll
                for (int u = 0; u < 4; u++)
#pragma unroll
                    for (int c = 0; c < 4; c++)
                        fma2(acc[u][c], hv[u], wb[c]);
            }
#pragma unroll
            for (int u = 0; u < 4; u++)
#pragma unroll
                for (int c = 0; c < 4; c++) {
                    ull o = __shfl_xor_sync(0xFFFFFFFFu, acc[u][c], 16);
                    add2(acc[u][c], o);
                }
            if (kg == 0) {
                ull* pl = ap + (size_t)(t & 1) * 16 * APW + w * APW;
#pragma unroll
                for (int u = 0; u < 4; u++) {
                    int npw = (n0 >> 1) + u;
                    ulonglong2 s0, s1;
                    s0.x = acc[u][0]; s0.y = acc[u][1];
                    s1.x = acc[u][2]; s1.y = acc[u][3];
                    *(ulonglong2*)(pl + npw * 18 + cg4)     = s0;
                    *(ulonglong2*)(pl + npw * 18 + cg4 + 2) = s1;
                }
            }
            // hand off partials; do NOT block
            asm volatile("membar.cta;");
            asm volatile("bar.arrive 1, %0;" :: "n"(NTH));
        }
    } else {
        // ================= reduce / gates warps (tid 512..575) =================
        const int rt = tid - 512;
        const int np = rt >> 2, jj = rt & 3;
        float c0v = 0.f, c1v = 0.f;      // cell state in registers
        float hn0 = 0.f, hn1 = 0.f;
        float xwr[2][4];
#pragma unroll
        for (int r = 0; r < 2; r++)
#pragma unroll
            for (int g = 0; g < 4; g++)
                xwr[r][g] = __ldcg(g_xw + ((size_t)(2 * np + r) * T_ + 0) * G4 + g * H_ + j0 + jj);

        for (int t = 0; t < T_; t++) {
            // wait for all 16 GEMM warps of this step
            asm volatile("bar.sync 1, %0;" :: "n"(NTH));

            const ull* base = ap + (size_t)(t & 1) * 16 * APW + np * 18 + jj;
            ull s0 = 0ULL, s1 = 0ULL, s2 = 0ULL, s3 = 0ULL;
#pragma unroll
            for (int p = 0; p < 16; p++) {
                const ull* pl = base + p * APW;
                add2(s0, pl[0]);
                add2(s1, pl[4]);
                add2(s2, pl[8]);
                add2(s3, pl[12]);
            }
            float a0l, a0h, a1l, a1h, a2l, a2h, a3l, a3h;
            unpack2(a0l, a0h, s0);
            unpack2(a1l, a1h, s1);
            unpack2(a2l, a2h, s2);
            unpack2(a3l, a3h, s3);

            float* hnb = &g_hbuf[(t + 1) & 1][0][0];
            {
                float ig = fsig(a0l + xwr[0][0]);
                float fg = fsig(a1l + xwr[0][1]);
                float og = fsig(a2l + xwr[0][2]);
                float gg = ftanh(a3l + xwr[0][3]);
                c0v = fg * c0v + ig * gg;
                hn0 = og * ftanh(c0v);
                hnb[(j0 + jj) * 32 + 2 * np] = hn0;
            }
            {
                float ig = fsig(a0h + xwr[1][0]);
                float fg = fsig(a1h + xwr[1][1]);
                float og = fsig(a2h + xwr[1][2]);
                float gg = ftanh(a3h + xwr[1][3]);
                c1v = fg * c1v + ig * gg;
                hn1 = og * ftanh(c1v);
                hnb[(j0 + jj) * 32 + 2 * np + 1] = hn1;
            }
            // both reduce warps done writing h -> publish flag
            asm volatile("bar.sync 2, 64;");
            if (rt == 0) {
                unsigned nf = (unsigned)t + 2u;
                asm volatile("st.release.gpu.global.u32 [%0], %1;" :: "l"(&g_flag[b]), "r"(nf));
            }
            // off critical path: out stores + next xw prefetch
            out[((size_t)(2 * np)     * T_ + t) * H_ + j0 + jj] = hn0;
            out[((size_t)(2 * np + 1) * T_ + t) * H_ + j0 + jj] = hn1;
            if (t + 1 < T_) {
#pragma unroll
                for (int r = 0; r < 2; r++)
#pragma unroll
                    for (int g = 0; g < 4; g++)
                        xwr[r][g] = __ldcg(g_xw + ((size_t)(2 * np + r) * T_ + (t + 1)) * G4 + g * H_ + j0 + jj);
            }
        }
    }
}

// ---------------- launch ----------------------------------------------------------
extern "C" void kernel_launch(void* const* d_in, const int* in_sizes, int n_in,
                              void* d_out, int out_size)
{
    const float* x    = (const float*)d_in[0];
    const float* h0   = (const float*)d_in[1];
    const float* Wx   = (const float*)d_in[2];
    const float* Wh   = (const float*)d_in[3];
    const float* bias = (const float*)d_in[4];
    float* out = (float*)d_out;

    init_state_kernel<<<64, 256>>>(h0);

    dim3 g1(G4 / 128, (N_ * T_) / 128);
    gemm_xw_kernel<<<g1, 256>>>(x, Wx, bias);

    const int shmem = 512 * 16 * 4 + 2 * 16 * APW * 8;
    cudaFuncSetAttribute(lstm_rec_kernel, cudaFuncAttributeMaxDynamicSharedMemorySize, shmem);
    lstm_rec_kernel<<<NB, NTH, shmem>>>(Wh, out);
}

// round 8
// speedup vs baseline: 1.7202x; 1.7202x over previous
#include <cuda_runtime.h>
#include <cstdint>
#include <math.h>

#define N_  32
#define T_  1024
#define D_  512
#define H_  512
#define G4  2048

#define NB   128
#define NTH  576    // 16 GEMM warps + 2 reduce warps
#define APW  288    // partial plane stride (ull), index np*18+c

typedef unsigned long long ull;

__device__ __forceinline__ void fma2(ull& d, const ull a, const ull b) {
    asm("fma.rn.f32x2 %0, %1, %2, %0;" : "+l"(d) : "l"(a), "l"(b));
}
__device__ __forceinline__ void add2(ull& d, const ull a) {
    asm("add.rn.f32x2 %0, %0, %1;" : "+l"(d) : "l"(a));
}
__device__ __forceinline__ ull bcast2(float x) {
    ull r; asm("mov.b64 %0, {%1, %1};" : "=l"(r) : "f"(x)); return r;
}
__device__ __forceinline__ void unpack2(float& lo, float& hi, ull a) {
    asm("mov.b64 {%0, %1}, %2;" : "=f"(lo), "=f"(hi) : "l"(a));
}
__device__ __forceinline__ float fsig(float x) { return 1.f / (1.f + __expf(-x)); }
__device__ __forceinline__ float ftanh(float x) { return 2.f / (1.f + __expf(-2.f * x)) - 1.f; }

// ---------------- device scratch -------------------------------------------------
__device__ float g_xw [(size_t)N_ * T_ * G4];        // phase1 out: [n][t][2048]
__device__ float g_xw2[(size_t)T_ * NB * 512];       // transposed: [t][b][n(32)][c(16)]
__device__ float g_hh [(size_t)(T_ + 1) * H_ * N_];  // h history: [t][j][n]
__device__ unsigned int g_grp[16 * 64];              // tree barrier (monotonic)
__device__ unsigned int g_root = 0;
__device__ volatile unsigned int g_gen = 0;

// ---------------- init: barrier reset + h0 -> g_hh[0] ----------------------------
__global__ void init_state_kernel(const float* __restrict__ h0)
{
    int i = blockIdx.x * blockDim.x + threadIdx.x;
    if (i < 16) g_grp[i * 64] = 0u;
    if (i == 16) g_root = 0u;
    if (i == 17) g_gen = 0u;
    if (i < H_ * N_) g_hh[i] = h0[(size_t)(i & 31) * H_ + (i >> 5)];  // [j][n] <- h0[n][j]
}

// ---------------- Phase 1: xw = x @ Wx + b (unchanged, proven) --------------------
__global__ __launch_bounds__(256, 2) void gemm_xw_kernel(const float* __restrict__ x,
                                                         const float* __restrict__ Wx,
                                                         const float* __restrict__ bias)
{
    __shared__ float As[8][128];
    __shared__ float Bs[8][128];
    const int tid = threadIdx.x;
    const int bm = blockIdx.y, bn = blockIdx.x;
    const int tx = tid & 15, ty = tid >> 4;
    const int a_row = tid >> 1, a_k = (tid & 1) << 2;
    const int b_row = tid >> 5, b_col = (tid & 31) << 2;

    const float* xA = x + (size_t)(bm * 128 + a_row) * D_ + a_k;
    const float* wB = Wx + (size_t)b_row * G4 + bn * 128 + b_col;

    ull accp[8][4];
#pragma unroll
    for (int i = 0; i < 8; i++)
#pragma unroll
        for (int j = 0; j < 4; j++) accp[i][j] = 0ULL;

    for (int k0 = 0; k0 < D_; k0 += 8) {
        float4 av = *(const float4*)(xA + k0);
        float4 bv = *(const float4*)(wB + (size_t)k0 * G4);
        __syncthreads();
        As[a_k + 0][a_row] = av.x;
        As[a_k + 1][a_row] = av.y;
        As[a_k + 2][a_row] = av.z;
        As[a_k + 3][a_row] = av.w;
        *(float4*)&Bs[b_row][b_col] = bv;
        __syncthreads();
#pragma unroll
        for (int kk = 0; kk < 8; kk++) {
            float a0[8];
            *(float4*)(a0)     = *(const float4*)&As[kk][ty * 8];
            *(float4*)(a0 + 4) = *(const float4*)&As[kk][ty * 8 + 4];
            ulonglong2 q0 = *(const ulonglong2*)&Bs[kk][tx * 8];
            ulonglong2 q1 = *(const ulonglong2*)&Bs[kk][tx * 8 + 4];
            ull b2[4] = {q0.x, q0.y, q1.x, q1.y};
            ull a2[8];
#pragma unroll
            for (int i = 0; i < 8; i++) a2[i] = bcast2(a0[i]);
#pragma unroll
            for (int i = 0; i < 8; i++)
#pragma unroll
                for (int j = 0; j < 4; j++)
                    fma2(accp[i][j], a2[i], b2[j]);
        }
    }

    ulonglong2 bq0 = *(const ulonglong2*)(bias + bn * 128 + tx * 8);
    ulonglong2 bq1 = *(const ulonglong2*)(bias + bn * 128 + tx * 8 + 4);
    ull bb2[4] = {bq0.x, bq0.y, bq1.x, bq1.y};
#pragma unroll
    for (int i = 0; i < 8; i++) {
#pragma unroll
        for (int j = 0; j < 4; j++) add2(accp[i][j], bb2[j]);
        size_t row = (size_t)(bm * 128 + ty * 8 + i);
        ulonglong2 s0, s1;
        s0.x = accp[i][0]; s0.y = accp[i][1];
        s1.x = accp[i][2]; s1.y = accp[i][3];
        *(ulonglong2*)(g_xw + row * G4 + bn * 128 + tx * 8)     = s0;
        *(ulonglong2*)(g_xw + row * G4 + bn * 128 + tx * 8 + 4) = s1;
    }
}

// ---------------- T1: g_xw[n][t][2048] -> g_xw2[t][b][n][c] ----------------------
// block: (b-octet = blockIdx.x, t = blockIdx.y), 512 threads, fully coalesced
__global__ __launch_bounds__(512) void xw_transpose_kernel()
{
    const int t  = blockIdx.y;
    const int b0 = blockIdx.x * 8;
    const int lane = threadIdx.x & 31;
    const int warp = threadIdx.x >> 5;      // 0..15
    const int gate = lane >> 3;             // 0..3
    const int bo   = lane & 7;              // 0..7
    const int b    = b0 + bo;
#pragma unroll
    for (int it = 0; it < 2; it++) {
        int n = warp + 16 * it;
        float4 v = __ldcg((const float4*)(g_xw + ((size_t)n * T_ + t) * G4 + gate * 512 + b * 4));
        *(float4*)(g_xw2 + ((size_t)t * NB + b) * 512 + n * 16 + gate * 4) = v;
    }
}

// ---------------- Phase 2: persistent recurrent (R6 skeleton) ---------------------
__device__ __forceinline__ void gridbar(int b, unsigned s)
{
    __syncthreads();
    if (threadIdx.x == 0) {
        __threadfence();
        unsigned old = atomicAdd(&g_grp[(b >> 3) * 64], 1u);
        if (old == 8u * s - 1u) {
            unsigned r = atomicAdd(&g_root, 1u);
            if (r == 16u * s - 1u) { __threadfence(); g_gen = s; }
        }
        while (g_gen < s) { }
    }
    __syncthreads();
}

extern __shared__ float smem_dyn[];

__global__ __launch_bounds__(NTH, 1) void lstm_rec_kernel(const float* __restrict__ Wh)
{
    // smem: ws[512][16] | hs[512][32] | ap ull[16][APW]
    float* ws = smem_dyn;                       // 8192 floats
    float* hs = ws + 512 * 16;                  // 16384 floats
    ull*   ap = (ull*)(hs + 512 * 32);          // 16*APW ull

    const int b   = blockIdx.x;
    const int tid = threadIdx.x;
    const int j0  = b * 4;

    for (int idx = tid; idx < 512 * 16; idx += NTH) {
        int k = idx >> 4, c = idx & 15;
        ws[idx] = Wh[(size_t)k * G4 + (c >> 2) * H_ + j0 + (c & 3)];
    }
    unsigned step = 1;
    gridbar(b, step); step++;

    const int w    = (tid < 512) ? (tid >> 5) : 0;
    const int lane = tid & 31;
    const int kg   = lane >> 4;
    const int pos  = lane & 15;
    const int n0   = (pos & 3) * 8;
    const int cg4  = (pos >> 2) * 4;
    const int kbase = w * 32 + kg * 16;

    // reduce/gates ids (tid >= 512): 64 threads, np = rt>>2, jj = rt&3
    const int rt = tid - 512;
    const int np = rt >> 2, jj = rt & 3;

    float c0v = 0.f, c1v = 0.f;
    float xwr[2][4];
    if (tid >= 512) {
        const float* xb = g_xw2 + (size_t)0 * NB * 512 + (size_t)b * 512;
#pragma unroll
        for (int r = 0; r < 2; r++)
#pragma unroll
            for (int g = 0; g < 4; g++)
                xwr[r][g] = __ldcg(xb + (2 * np + r) * 16 + g * 4 + jj);
    }

    for (int t = 0; t < T_; t++) {
        if (tid < 512) {
            // ---- GEMM warps ----
            const float* hb = g_hh + (size_t)t * (H_ * N_);
            {
                int chunk = (lane & 7) * 4;
#pragma unroll
                for (int rr = 0; rr < 8; rr++) {
                    int row = w * 32 + rr * 4 + (lane >> 3);
                    float4 v = __ldcg((const float4*)(hb + row * 32 + chunk));
                    *(float4*)(hs + row * 32 + chunk) = v;
                }
            }
            __syncwarp();

            ull acc[4][4];
#pragma unroll
            for (int u = 0; u < 4; u++)
#pragma unroll
                for (int c = 0; c < 4; c++) acc[u][c] = 0ULL;

#pragma unroll
            for (int i = 0; i < 16; i++) {
                int k = kbase + i;
                const float* hr = hs + k * 32 + n0;
                ulonglong2 hA = *(const ulonglong2*)hr;
                ulonglong2 hB = *(const ulonglong2*)(hr + 4);
                ull hv[4] = {hA.x, hA.y, hB.x, hB.y};
                float4 wf = *(const float4*)(ws + k * 16 + cg4);
                ull wb[4] = {bcast2(wf.x), bcast2(wf.y), bcast2(wf.z), bcast2(wf.w)};
#pragma unroll
                for (int u = 0; u < 4; u++)
#pragma unroll
                    for (int c = 0; c < 4; c++)
                        fma2(acc[u][c], hv[u], wb[c]);
            }
#pragma unroll
            for (int u = 0; u < 4; u++)
#pragma unroll
                for (int c = 0; c < 4; c++) {
                    ull o = __shfl_xor_sync(0xFFFFFFFFu, acc[u][c], 16);
                    add2(acc[u][c], o);
                }
            if (kg == 0) {
                ull* pl = ap + w * APW;
#pragma unroll
                for (int u = 0; u < 4; u++) {
                    int npw = (n0 >> 1) + u;
                    ulonglong2 s0, s1;
                    s0.x = acc[u][0]; s0.y = acc[u][1];
                    s1.x = acc[u][2]; s1.y = acc[u][3];
                    *(ulonglong2*)(pl + npw * 18 + cg4)     = s0;
                    *(ulonglong2*)(pl + npw * 18 + cg4 + 2) = s1;
                }
            }
            __syncthreads();   // partials visible to reduce warps
            __syncthreads();   // reduce done (paired with reduce side)
        } else {
            // ---- reduce / gates (64 active threads) ----
            __syncthreads();   // wait for partials

            const ull* base = ap + np * 18 + jj;
            ull s0 = 0ULL, s1 = 0ULL, s2 = 0ULL, s3 = 0ULL;
#pragma unroll
            for (int p = 0; p < 16; p++) {
                const ull* pl = base + p * APW;
                add2(s0, pl[0]);
                add2(s1, pl[4]);
                add2(s2, pl[8]);
                add2(s3, pl[12]);
            }
            if (rt < 64) {
                float a0l, a0h, a1l, a1h, a2l, a2h, a3l, a3h;
                unpack2(a0l, a0h, s0);
                unpack2(a1l, a1h, s1);
                unpack2(a2l, a2h, s2);
                unpack2(a3l, a3h, s3);

                float ig0 = fsig(a0l + xwr[0][0]);
                float fg0 = fsig(a1l + xwr[0][1]);
                float og0 = fsig(a2l + xwr[0][2]);
                float gg0 = ftanh(a3l + xwr[0][3]);
                c0v = fg0 * c0v + ig0 * gg0;
                float hn0 = og0 * ftanh(c0v);

                float ig1 = fsig(a0h + xwr[1][0]);
                float fg1 = fsig(a1h + xwr[1][1]);
                float og1 = fsig(a2h + xwr[1][2]);
                float gg1 = ftanh(a3h + xwr[1][3]);
                c1v = fg1 * c1v + ig1 * gg1;
                float hn1 = og1 * ftanh(c1v);

                float2 hv2; hv2.x = hn0; hv2.y = hn1;
                *(float2*)(g_hh + (size_t)(t + 1) * (H_ * N_) + (j0 + jj) * 32 + 2 * np) = hv2;

                if (t + 1 < T_) {
                    const float* xb = g_xw2 + ((size_t)(t + 1) * NB + b) * 512;
#pragma unroll
                    for (int r = 0; r < 2; r++)
#pragma unroll
                        for (int g = 0; g < 4; g++)
                            xwr[r][g] = __ldcg(xb + (2 * np + r) * 16 + g * 4 + jj);
                }
            }
            __syncthreads();   // h stored; pairs with GEMM side's 2nd sync
        }
        gridbar(b, step); step++;
    }
}

// ---------------- T2: g_hh[t+1][j][n] -> out[n][t][j] -----------------------------
__global__ __launch_bounds__(512) void out_transpose_kernel(float* __restrict__ out)
{
    extern __shared__ float sm[];
    const int t = blockIdx.x;
    const int tid = threadIdx.x;
    const float* src = g_hh + (size_t)(t + 1) * (H_ * N_);
#pragma unroll
    for (int it = 0; it < 8; it++) {
        int idx = tid + it * 512;
        *(float4*)(sm + idx * 4) = __ldcg((const float4*)(src + idx * 4));
    }
    __syncthreads();
    const int b8 = tid & 7, n = (tid >> 3) & 31, bh = tid >> 8;  // bh 0..1
#pragma unroll
    for (int it = 0; it < 8; it++) {
        int b = b8 + bh * 8 + it * 16;
        float4 v;
        v.x = sm[(b * 4 + 0) * 32 + n];
        v.y = sm[(b * 4 + 1) * 32 + n];
        v.z = sm[(b * 4 + 2) * 32 + n];
        v.w = sm[(b * 4 + 3) * 32 + n];
        *(float4*)(out + ((size_t)n * T_ + t) * H_ + b * 4) = v;
    }
}

// ---------------- launch ----------------------------------------------------------
extern "C" void kernel_launch(void* const* d_in, const int* in_sizes, int n_in,
                              void* d_out, int out_size)
{
    const float* x    = (const float*)d_in[0];
    const float* h0   = (const float*)d_in[1];
    const float* Wx   = (const float*)d_in[2];
    const float* Wh   = (const float*)d_in[3];
    const float* bias = (const float*)d_in[4];
    float* out = (float*)d_out;

    init_state_kernel<<<64, 256>>>(h0);

    dim3 g1(G4 / 128, (N_ * T_) / 128);
    gemm_xw_kernel<<<g1, 256>>>(x, Wx, bias);

    dim3 gt1(16, T_);
    xw_transpose_kernel<<<gt1, 512>>>();

    const int shmem = (512 * 16 + 512 * 32) * 4 + 16 * APW * 8;
    cudaFuncSetAttribute(lstm_rec_kernel, cudaFuncAttributeMaxDynamicSharedMemorySize, shmem);
    lstm_rec_kernel<<<NB, NTH, shmem>>>(Wh);

    cudaFuncSetAttribute(out_transpose_kernel, cudaFuncAttributeMaxDynamicSharedMemorySize, 65536);
    out_transpose_kernel<<<T_, 512, 65536>>>(out);
}

// round 10
// speedup vs baseline: 1.8649x; 1.0841x over previous
#include <cuda_runtime.h>
#include <cstdint>
#include <math.h>

#define N_  32
#define T_  1024
#define D_  512
#define H_  512
#define G4  2048

#define NB   128
#define NTH  576    // 16 GEMM warps + 2 reduce warps
#define APW  288    // partial plane stride (ull): 4 np * 72

typedef unsigned long long ull;

__device__ __forceinline__ void fma2(ull& d, const ull a, const ull b) {
    asm("fma.rn.f32x2 %0, %1, %2, %0;" : "+l"(d) : "l"(a), "l"(b));
}
__device__ __forceinline__ void add2(ull& d, const ull a) {
    asm("add.rn.f32x2 %0, %0, %1;" : "+l"(d) : "l"(a));
}
__device__ __forceinline__ ull bcast2(float x) {
    ull r; asm("mov.b64 %0, {%1, %1};" : "=l"(r) : "f"(x)); return r;
}
__device__ __forceinline__ void unpack2(float& lo, float& hi, ull a) {
    asm("mov.b64 {%0, %1}, %2;" : "=f"(lo), "=f"(hi) : "l"(a));
}
__device__ __forceinline__ float fsig(float x) { return 1.f / (1.f + __expf(-x)); }
__device__ __forceinline__ float ftanh(float x) { return 2.f / (1.f + __expf(-2.f * x)) - 1.f; }

// ---------------- device scratch -------------------------------------------------
__device__ float g_xw [(size_t)N_ * T_ * G4];          // phase1 out: [n][t][2048]
__device__ float g_xw2[(size_t)T_ * NB * 512];         // [t][cta][n8][gate][j16]
__device__ float g_hT [(size_t)(T_ + 1) * 4 * 4096];   // h history: [t][g][k(512)][n8(8)]
__device__ unsigned int g_grp[16 * 64];                // 4 groups x 4 subgroups
__device__ unsigned int g_root[4 * 64];
__device__ volatile unsigned int g_gen[4 * 64];

// ---------------- init: barriers + h0 -> g_hT[0] ----------------------------------
__global__ void init_state_kernel(const float* __restrict__ h0)
{
    int i = blockIdx.x * blockDim.x + threadIdx.x;
    if (i < 16) g_grp[i * 64] = 0u;
    if (i >= 16 && i < 20) g_root[(i - 16) * 64] = 0u;
    if (i >= 20 && i < 24) g_gen[(i - 20) * 64] = 0u;
    if (i < 4 * 512 * 8) {
        int g = i >> 12, k = (i >> 3) & 511, n8 = i & 7;
        g_hT[(size_t)g * 4096 + k * 8 + n8] = h0[(size_t)(g * 8 + n8) * H_ + k];
    }
}

// ---------------- Phase 1: xw = x @ Wx + b (unchanged, proven) --------------------
__global__ __launch_bounds__(256, 2) void gemm_xw_kernel(const float* __restrict__ x,
                                                         const float* __restrict__ Wx,
                                                         const float* __restrict__ bias)
{
    __shared__ float As[8][128];
    __shared__ float Bs[8][128];
    const int tid = threadIdx.x;
    const int bm = blockIdx.y, bn = blockIdx.x;
    const int tx = tid & 15, ty = tid >> 4;
    const int a_row = tid >> 1, a_k = (tid & 1) << 2;
    const int b_row = tid >> 5, b_col = (tid & 31) << 2;

    const float* xA = x + (size_t)(bm * 128 + a_row) * D_ + a_k;
    const float* wB = Wx + (size_t)b_row * G4 + bn * 128 + b_col;

    ull accp[8][4];
#pragma unroll
    for (int i = 0; i < 8; i++)
#pragma unroll
        for (int j = 0; j < 4; j++) accp[i][j] = 0ULL;

    for (int k0 = 0; k0 < D_; k0 += 8) {
        float4 av = *(const float4*)(xA + k0);
        float4 bv = *(const float4*)(wB + (size_t)k0 * G4);
        __syncthreads();
        As[a_k + 0][a_row] = av.x;
        As[a_k + 1][a_row] = av.y;
        As[a_k + 2][a_row] = av.z;
        As[a_k + 3][a_row] = av.w;
        *(float4*)&Bs[b_row][b_col] = bv;
        __syncthreads();
#pragma unroll
        for (int kk = 0; kk < 8; kk++) {
            float a0[8];
            *(float4*)(a0)     = *(const float4*)&As[kk][ty * 8];
            *(float4*)(a0 + 4) = *(const float4*)&As[kk][ty * 8 + 4];
            ulonglong2 q0 = *(const ulonglong2*)&Bs[kk][tx * 8];
            ulonglong2 q1 = *(const ulonglong2*)&Bs[kk][tx * 8 + 4];
            ull b2[4] = {q0.x, q0.y, q1.x, q1.y};
            ull a2[8];
#pragma unroll
            for (int i = 0; i < 8; i++) a2[i] = bcast2(a0[i]);
#pragma unroll
            for (int i = 0; i < 8; i++)
#pragma unroll
                for (int j = 0; j < 4; j++)
                    fma2(accp[i][j], a2[i], b2[j]);
        }
    }

    ulonglong2 bq0 = *(const ulonglong2*)(bias + bn * 128 + tx * 8);
    ulonglong2 bq1 = *(const ulonglong2*)(bias + bn * 128 + tx * 8 + 4);
    ull bb2[4] = {bq0.x, bq0.y, bq1.x, bq1.y};
#pragma unroll
    for (int i = 0; i < 8; i++) {
#pragma unroll
        for (int j = 0; j < 4; j++) add2(accp[i][j], bb2[j]);
        size_t row = (size_t)(bm * 128 + ty * 8 + i);
        ulonglong2 s0, s1;
        s0.x = accp[i][0]; s0.y = accp[i][1];
        s1.x = accp[i][2]; s1.y = accp[i][3];
        *(ulonglong2*)(g_xw + row * G4 + bn * 128 + tx * 8)     = s0;
        *(ulonglong2*)(g_xw + row * G4 + bn * 128 + tx * 8 + 4) = s1;
    }
}

// ---------------- T1: g_xw[n][t][2048] -> g_xw2[t][cta][n8][gate][j16] -------------
__global__ __launch_bounds__(512) void xw_transpose_kernel()
{
    const int t = blockIdx.x;
    const int g = blockIdx.y;
#pragma unroll
    for (int it = 0; it < 8; it++) {
        int flat = it * 512 + threadIdx.x;          // (r, n8, gate, jl4)
        int r    = flat >> 7;
        int n8   = (flat >> 4) & 7;
        int gate = (flat >> 2) & 3;
        int jl4  = flat & 3;
        float4 v = __ldcg((const float4*)(g_xw +
                    ((size_t)(g * 8 + n8) * T_ + t) * G4 + gate * 512 + r * 16 + jl4 * 4));
        *(float4*)(g_xw2 + (((size_t)t * NB + g * 32 + r) * 8 + n8) * 64
                         + gate * 16 + jl4 * 4) = v;
    }
}

// ---------------- Phase 2: per-group persistent recurrent -------------------------
__device__ __forceinline__ void gridbar(int g, int r, unsigned s)
{
    __syncthreads();
    if (threadIdx.x == 0) {
        __threadfence();
        unsigned old = atomicAdd(&g_grp[(g * 4 + (r >> 3)) * 64], 1u);
        if (old == 8u * s - 1u) {
            unsigned rr = atomicAdd(&g_root[g * 64], 1u);
            if (rr == 4u * s - 1u) { __threadfence(); g_gen[g * 64] = s; }
        }
        while (g_gen[g * 64] < s) { }
    }
    __syncthreads();
}

extern __shared__ float smem_dyn[];

__global__ __launch_bounds__(NTH, 1) void lstm_rec_kernel(const float* __restrict__ Wh)
{
    // smem: ws[512][64] (128KB) | hs[512][8] (16KB) | ap ull[16][APW] (36KB)
    float* ws = smem_dyn;
    float* hs = ws + 512 * 64;
    ull*   ap = (ull*)(hs + 512 * 8);

    const int b   = blockIdx.x;
    const int g   = b >> 5;          // group 0..3 (batch n = g*8 .. g*8+7)
    const int r   = b & 31;          // rank: j-columns [r*16, r*16+16)
    const int tid = threadIdx.x;

    // weights: ws[k][c], c = gate*16 + jl  ->  Wh[k][gate*512 + r*16 + jl]
    for (int idx = tid; idx < 512 * 64; idx += NTH) {
        int k = idx >> 6, c = idx & 63;
        ws[idx] = Wh[(size_t)k * G4 + (c >> 4) * 512 + r * 16 + (c & 15)];
    }
    unsigned step = 1;
    gridbar(g, r, step); step++;

    const int w    = (tid < 512) ? (tid >> 5) : 0;   // GEMM warp, k in [w*32, w*32+32)
    const int lane = tid & 31;
    const int kg   = lane >> 4;
    const int pos  = lane & 15;
    const int cg4  = pos * 4;                        // 4 c's: cg4..cg4+3
    const int kbase = w * 32 + kg * 16;

    // reduce ids (tid >= 512): rt 0..63: np = rt>>4 (0..3), j = rt&15
    const int rt = tid - 512;
    const int np = rt >> 4, jc = rt & 15;

    float c0v = 0.f, c1v = 0.f;
    float xwr[2][4];
    if (tid >= 512) {
        const float* xb = g_xw2 + (size_t)b * 512;
#pragma unroll
        for (int rr = 0; rr < 2; rr++)
#pragma unroll
            for (int q = 0; q < 4; q++)
                xwr[rr][q] = __ldcg(xb + (2 * np + rr) * 64 + q * 16 + jc);
    }

    for (int t = 0; t < T_; t++) {
        if (tid < 512) {
            // ---- stage own k-slice of h: TWO float4 per lane (all 32 rows) ----
            const float* hb = g_hT + ((size_t)t * 4 + g) * 4096;
            {
                int off = (w * 32 + (lane >> 1)) * 8 + (lane & 1) * 4;
                float4 v0 = __ldcg((const float4*)(hb + off));
                float4 v1 = __ldcg((const float4*)(hb + off + 128));  // rows +16
                *(float4*)(hs + off) = v0;
                *(float4*)(hs + off + 128) = v1;
            }
            __syncwarp();

            // ---- GEMM: acc[np 4][c 4] over own 16 k's, n-packed f32x2 ----
            ull acc[4][4];
#pragma unroll
            for (int u = 0; u < 4; u++)
#pragma unroll
                for (int c = 0; c < 4; c++) acc[u][c] = 0ULL;

#pragma unroll
            for (int i = 0; i < 16; i++) {
                int k = kbase + i;
                ulonglong2 hA = *(const ulonglong2*)(hs + k * 8);
                ulonglong2 hB = *(const ulonglong2*)(hs + k * 8 + 4);
                ull hv[4] = {hA.x, hA.y, hB.x, hB.y};
                float4 wf = *(const float4*)(ws + k * 64 + cg4);
                ull wb[4] = {bcast2(wf.x), bcast2(wf.y), bcast2(wf.z), bcast2(wf.w)};
#pragma unroll
                for (int u = 0; u < 4; u++)
#pragma unroll
                    for (int c = 0; c < 4; c++)
                        fma2(acc[u][c], hv[u], wb[c]);
            }
#pragma unroll
            for (int u = 0; u < 4; u++)
#pragma unroll
                for (int c = 0; c < 4; c++) {
                    ull o = __shfl_xor_sync(0xFFFFFFFFu, acc[u][c], 16);
                    add2(acc[u][c], o);
                }
            if (kg == 0) {
                ull* pl = ap + w * APW;
#pragma unroll
                for (int u = 0; u < 4; u++) {
                    ulonglong2 s0, s1;
                    s0.x = acc[u][0]; s0.y = acc[u][1];
                    s1.x = acc[u][2]; s1.y = acc[u][3];
                    *(ulonglong2*)(pl + u * 72 + cg4)     = s0;
                    *(ulonglong2*)(pl + u * 72 + cg4 + 2) = s1;
                }
            }
            __syncthreads();   // partials -> reduce warps
            __syncthreads();   // reduce done
        } else {
            __syncthreads();   // wait for partials

            // ---- reduce 16 planes, 4 gate cells per thread ----
            ull s0 = 0ULL, s1 = 0ULL, s2 = 0ULL, s3 = 0ULL;
            const ull* base = ap + np * 72 + jc;
#pragma unroll
            for (int p = 0; p < 16; p++) {
                const ull* pl = base + p * APW;
                add2(s0, pl[0]);
                add2(s1, pl[16]);
                add2(s2, pl[32]);
                add2(s3, pl[48]);
            }
            float a0l, a0h, a1l, a1h, a2l, a2h, a3l, a3h;
            unpack2(a0l, a0h, s0);
            unpack2(a1l, a1h, s1);
            unpack2(a2l, a2h, s2);
            unpack2(a3l, a3h, s3);

            float ig0 = fsig(a0l + xwr[0][0]);
            float fg0 = fsig(a1l + xwr[0][1]);
            float og0 = fsig(a2l + xwr[0][2]);
            float gg0 = ftanh(a3l + xwr[0][3]);
            c0v = fg0 * c0v + ig0 * gg0;
            float hn0 = og0 * ftanh(c0v);

            float ig1 = fsig(a0h + xwr[1][0]);
            float fg1 = fsig(a1h + xwr[1][1]);
            float og1 = fsig(a2h + xwr[1][2]);
            float gg1 = ftanh(a3h + xwr[1][3]);
            c1v = fg1 * c1v + ig1 * gg1;
            float hn1 = og1 * ftanh(c1v);

            float2 hv2; hv2.x = hn0; hv2.y = hn1;
            *(float2*)(g_hT + ((size_t)(t + 1) * 4 + g) * 4096 + (r * 16 + jc) * 8 + 2 * np) = hv2;

            // off critical path: next xw prefetch
            if (t + 1 < T_) {
                const float* xb = g_xw2 + ((size_t)(t + 1) * NB + b) * 512;
#pragma unroll
                for (int rr = 0; rr < 2; rr++)
#pragma unroll
                    for (int q = 0; q < 4; q++)
                        xwr[rr][q] = __ldcg(xb + (2 * np + rr) * 64 + q * 16 + jc);
            }
            __syncthreads();   // h published (pairs with GEMM 2nd sync)
        }
        gridbar(g, r, step); step++;
    }
}

// ---------------- T2: g_hT[t+1][g][j][n8] -> out[n][t][j] --------------------------
__global__ __launch_bounds__(512) void out_transpose_kernel(float* __restrict__ out)
{
    extern __shared__ float sm[];
    const int t = blockIdx.x;
    const int tid = threadIdx.x;
    const float* src = g_hT + (size_t)(t + 1) * 4 * 4096;
#pragma unroll
    for (int it = 0; it < 8; it++) {
        int idx = tid + it * 512;
        *(float4*)(sm + idx * 4) = __ldcg((const float4*)(src + idx * 4));
    }
    __syncthreads();
    const int n = tid >> 4, jb = (tid & 15) * 32;
    const int gbase = (n >> 3) * 4096, n8 = n & 7;
#pragma unroll
    for (int it = 0; it < 8; it++) {
        int j = jb + it * 4;
        float4 v;
        v.x = sm[gbase + (j + 0) * 8 + n8];
        v.y = sm[gbase + (j + 1) * 8 + n8];
        v.z = sm[gbase + (j + 2) * 8 + n8];
        v.w = sm[gbase + (j + 3) * 8 + n8];
        *(float4*)(out + ((size_t)n * T_ + t) * H_ + j) = v;
    }
}

// ---------------- launch ----------------------------------------------------------
extern "C" void kernel_launch(void* const* d_in, const int* in_sizes, int n_in,
                              void* d_out, int out_size)
{
    const float* x    = (const float*)d_in[0];
    const float* h0   = (const float*)d_in[1];
    const float* Wx   = (const float*)d_in[2];
    const float* Wh   = (const float*)d_in[3];
    const float* bias = (const float*)d_in[4];
    float* out = (float*)d_out;

    init_state_kernel<<<64, 256>>>(h0);

    dim3 g1(G4 / 128, (N_ * T_) / 128);
    gemm_xw_kernel<<<g1, 256>>>(x, Wx, bias);

    dim3 gt1(T_, 4);
    xw_transpose_kernel<<<gt1, 512>>>();

    const int shmem = (512 * 64 + 512 * 8) * 4 + 16 * APW * 8;
    cudaFuncSetAttribute(lstm_rec_kernel, cudaFuncAttributeMaxDynamicSharedMemorySize, shmem);
    lstm_rec_kernel<<<NB, NTH, shmem>>>(Wh);

    cudaFuncSetAttribute(out_transpose_kernel, cudaFuncAttributeMaxDynamicSharedMemorySize, 65536);
    out_transpose_kernel<<<T_, 512, 65536>>>(out);
}

// round 11
// speedup vs baseline: 2.2927x; 1.2294x over previous
#include <cuda_runtime.h>
#include <cstdint>
#include <math.h>

#define N_  32
#define T_  1024
#define D_  512
#define H_  512
#define G4  2048

#define NB   128
#define NTH  576    // 16 GEMM warps + 2 reduce warps
#define APW  288    // partial plane stride (ull): 4 np * 72

typedef unsigned long long ull;

__device__ __forceinline__ void fma2(ull& d, const ull a, const ull b) {
    asm("fma.rn.f32x2 %0, %1, %2, %0;" : "+l"(d) : "l"(a), "l"(b));
}
__device__ __forceinline__ void add2(ull& d, const ull a) {
    asm("add.rn.f32x2 %0, %0, %1;" : "+l"(d) : "l"(a));
}
__device__ __forceinline__ ull bcast2(float x) {
    ull r; asm("mov.b64 %0, {%1, %1};" : "=l"(r) : "f"(x)); return r;
}
__device__ __forceinline__ void unpack2(float& lo, float& hi, ull a) {
    asm("mov.b64 {%0, %1}, %2;" : "=f"(lo), "=f"(hi) : "l"(a));
}
__device__ __forceinline__ float fsig(float x) { return 1.f / (1.f + __expf(-x)); }
__device__ __forceinline__ float ftanh(float x) { return 2.f / (1.f + __expf(-2.f * x)) - 1.f; }

// ---- cp.async helpers ----
__device__ __forceinline__ void cp_async16(void* dst, const void* src) {
    unsigned s = (unsigned)__cvta_generic_to_shared(dst);
    asm volatile("cp.async.cg.shared.global [%0], [%1], 16;" :: "r"(s), "l"(src));
}
__device__ __forceinline__ void cp_commit() {
    asm volatile("cp.async.commit_group;" ::: "memory");
}
template <int NN> __device__ __forceinline__ void cp_wait() {
    asm volatile("cp.async.wait_group %0;" :: "n"(NN) : "memory");
}

// ---- tf32 mma helpers ----
__device__ __forceinline__ uint32_t f2tf(float x) {
    uint32_t r; asm("cvt.rna.tf32.f32 %0, %1;" : "=r"(r) : "f"(x)); return r;
}
__device__ __forceinline__ void mma_tf32(float* c, const uint32_t* a, const uint32_t* b) {
    asm("mma.sync.aligned.m16n8k8.row.col.f32.tf32.tf32.f32 "
        "{%0,%1,%2,%3},{%4,%5,%6,%7},{%8,%9},{%0,%1,%2,%3};"
        : "+f"(c[0]), "+f"(c[1]), "+f"(c[2]), "+f"(c[3])
        : "r"(a[0]), "r"(a[1]), "r"(a[2]), "r"(a[3]), "r"(b[0]), "r"(b[1]));
}

// ---------------- device scratch -------------------------------------------------
__device__ float g_xw [(size_t)N_ * T_ * G4];          // phase1 out: [n][t][2048]
__device__ float g_xw2[(size_t)T_ * NB * 512];         // [t][cta][n8][gate][j16]
__device__ float g_hT [(size_t)(T_ + 1) * 4 * 4096];   // h history: [t][g][k(512)][n8(8)]
__device__ unsigned int g_grp[16 * 64];                // 4 groups x 4 subgroups
__device__ unsigned int g_root[4 * 64];
__device__ volatile unsigned int g_gen[4 * 64];

// ---------------- init: barriers + h0 -> g_hT[0] ----------------------------------
__global__ void init_state_kernel(const float* __restrict__ h0)
{
    int i = blockIdx.x * blockDim.x + threadIdx.x;
    if (i < 16) g_grp[i * 64] = 0u;
    if (i >= 16 && i < 20) g_root[(i - 16) * 64] = 0u;
    if (i >= 20 && i < 24) g_gen[(i - 20) * 64] = 0u;
    if (i < 4 * 512 * 8) {
        int g = i >> 12, k = (i >> 3) & 511, n8 = i & 7;
        g_hT[(size_t)g * 4096 + k * 8 + n8] = h0[(size_t)(g * 8 + n8) * H_ + k];
    }
}

// ---------------- Phase 1: xw = x @ Wx + b  via tf32 tensor cores ------------------
// CTA tile 128x128, 8 warps (2x4), warp tile 64x32, K-chunk 32, double-buffered
#define AS_STR 40    // A smem row stride (floats), [m][k]
#define BS_STR 132   // B smem row stride (floats), [k][n]
#define AS_BUF (128 * AS_STR)
#define BS_BUF (32 * BS_STR)

__global__ __launch_bounds__(256) void gemm_xw_tc(const float* __restrict__ x,
                                                  const float* __restrict__ Wx,
                                                  const float* __restrict__ bias)
{
    extern __shared__ float sm1[];
    float* As = sm1;                    // [2][128][AS_STR]
    float* Bs = sm1 + 2 * AS_BUF;       // [2][32][BS_STR]

    const int tid  = threadIdx.x;
    const int bn   = blockIdx.x, bm = blockIdx.y;
    const int warp = tid >> 5, lane = tid & 31;
    const int wy = warp & 1, wx = warp >> 1;     // warp grid 2(m) x 4(n)
    const int g  = lane >> 2, tg = lane & 3;

    float acc[4][4][4];
#pragma unroll
    for (int mi = 0; mi < 4; mi++)
#pragma unroll
        for (int ni = 0; ni < 4; ni++)
#pragma unroll
            for (int c = 0; c < 4; c++) acc[mi][ni][c] = 0.f;

    // prologue: stage k0=0 into buf 0
    {
#pragma unroll
        for (int i = 0; i < 4; i++) {
            int flat = i * 256 + tid;
            int m = flat >> 3, kc = flat & 7;
            cp_async16(As + m * AS_STR + kc * 4,
                       x + (size_t)(bm * 128 + m) * D_ + kc * 4);
        }
#pragma unroll
        for (int i = 0; i < 4; i++) {
            int flat = i * 256 + tid;
            int k = flat >> 5, nc = flat & 31;
            cp_async16(Bs + k * BS_STR + nc * 4,
                       Wx + (size_t)k * G4 + bn * 128 + nc * 4);
        }
        cp_commit();
    }

    for (int it = 0; it < 16; it++) {
        if (it < 15) {
            const int k0 = (it + 1) * 32;
            const int nb = (it + 1) & 1;
#pragma unroll
            for (int i = 0; i < 4; i++) {
                int flat = i * 256 + tid;
                int m = flat >> 3, kc = flat & 7;
                cp_async16(As + nb * AS_BUF + m * AS_STR + kc * 4,
                           x + (size_t)(bm * 128 + m) * D_ + k0 + kc * 4);
            }
#pragma unroll
            for (int i = 0; i < 4; i++) {
                int flat = i * 256 + tid;
                int k = flat >> 5, nc = flat & 31;
                cp_async16(Bs + nb * BS_BUF + k * BS_STR + nc * 4,
                           Wx + (size_t)(k0 + k) * G4 + bn * 128 + nc * 4);
            }
            cp_commit();
            cp_wait<1>();
        } else {
            cp_wait<0>();
        }
        __syncthreads();

        const float* Ab = As + (it & 1) * AS_BUF;
        const float* Bb = Bs + (it & 1) * BS_BUF;
#pragma unroll
        for (int ks = 0; ks < 4; ks++) {
            uint32_t af[4][4], bf[4][2];
#pragma unroll
            for (int mi = 0; mi < 4; mi++) {
                const float* ap_ = Ab + (wy * 64 + mi * 16) * AS_STR + ks * 8;
                af[mi][0] = f2tf(ap_[ g      * AS_STR + tg    ]);
                af[mi][1] = f2tf(ap_[(g + 8) * AS_STR + tg    ]);
                af[mi][2] = f2tf(ap_[ g      * AS_STR + tg + 4]);
                af[mi][3] = f2tf(ap_[(g + 8) * AS_STR + tg + 4]);
            }
#pragma unroll
            for (int ni = 0; ni < 4; ni++) {
                const float* bp_ = Bb + ks * 8 * BS_STR + wx * 32 + ni * 8 + g;
                bf[ni][0] = f2tf(bp_[ tg      * BS_STR]);
                bf[ni][1] = f2tf(bp_[(tg + 4) * BS_STR]);
            }
#pragma unroll
            for (int mi = 0; mi < 4; mi++)
#pragma unroll
                for (int ni = 0; ni < 4; ni++)
                    mma_tf32(acc[mi][ni], af[mi], bf[ni]);
        }
        __syncthreads();
    }

    // bias + store
#pragma unroll
    for (int ni = 0; ni < 4; ni++) {
        int col = bn * 128 + wx * 32 + ni * 8 + 2 * tg;
        float b0 = bias[col], b1 = bias[col + 1];
#pragma unroll
        for (int mi = 0; mi < 4; mi++) {
            int row0 = bm * 128 + wy * 64 + mi * 16 + g;
            float2 v0; v0.x = acc[mi][ni][0] + b0; v0.y = acc[mi][ni][1] + b1;
            float2 v1; v1.x = acc[mi][ni][2] + b0; v1.y = acc[mi][ni][3] + b1;
            *(float2*)(g_xw + (size_t)row0 * G4 + col)       = v0;
            *(float2*)(g_xw + (size_t)(row0 + 8) * G4 + col) = v1;
        }
    }
}

// ---------------- T1: g_xw[n][t][2048] -> g_xw2[t][cta][n8][gate][j16] -------------
__global__ __launch_bounds__(512) void xw_transpose_kernel()
{
    const int t = blockIdx.x;
    const int g = blockIdx.y;
#pragma unroll
    for (int it = 0; it < 8; it++) {
        int flat = it * 512 + threadIdx.x;          // (r, n8, gate, jl4)
        int r    = flat >> 7;
        int n8   = (flat >> 4) & 7;
        int gate = (flat >> 2) & 3;
        int jl4  = flat & 3;
        float4 v = __ldcg((const float4*)(g_xw +
                    ((size_t)(g * 8 + n8) * T_ + t) * G4 + gate * 512 + r * 16 + jl4 * 4));
        *(float4*)(g_xw2 + (((size_t)t * NB + g * 32 + r) * 8 + n8) * 64
                         + gate * 16 + jl4 * 4) = v;
    }
}

// ---------------- Phase 2: per-group persistent recurrent (unchanged R10) ---------
__device__ __forceinline__ void gridbar(int g, int r, unsigned s)
{
    __syncthreads();
    if (threadIdx.x == 0) {
        __threadfence();
        unsigned old = atomicAdd(&g_grp[(g * 4 + (r >> 3)) * 64], 1u);
        if (old == 8u * s - 1u) {
            unsigned rr = atomicAdd(&g_root[g * 64], 1u);
            if (rr == 4u * s - 1u) { __threadfence(); g_gen[g * 64] = s; }
        }
        while (g_gen[g * 64] < s) { }
    }
    __syncthreads();
}

extern __shared__ float smem_dyn[];

__global__ __launch_bounds__(NTH, 1) void lstm_rec_kernel(const float* __restrict__ Wh)
{
    float* ws = smem_dyn;
    float* hs = ws + 512 * 64;
    ull*   ap = (ull*)(hs + 512 * 8);

    const int b   = blockIdx.x;
    const int g   = b >> 5;
    const int r   = b & 31;
    const int tid = threadIdx.x;

    for (int idx = tid; idx < 512 * 64; idx += NTH) {
        int k = idx >> 6, c = idx & 63;
        ws[idx] = Wh[(size_t)k * G4 + (c >> 4) * 512 + r * 16 + (c & 15)];
    }
    unsigned step = 1;
    gridbar(g, r, step); step++;

    const int w    = (tid < 512) ? (tid >> 5) : 0;
    const int lane = tid & 31;
    const int kg   = lane >> 4;
    const int pos  = lane & 15;
    const int cg4  = pos * 4;
    const int kbase = w * 32 + kg * 16;

    const int rt = tid - 512;
    const int np = rt >> 4, jc = rt & 15;

    float c0v = 0.f, c1v = 0.f;
    float xwr[2][4];
    if (tid >= 512) {
        const float* xb = g_xw2 + (size_t)b * 512;
#pragma unroll
        for (int rr = 0; rr < 2; rr++)
#pragma unroll
            for (int q = 0; q < 4; q++)
                xwr[rr][q] = __ldcg(xb + (2 * np + rr) * 64 + q * 16 + jc);
    }

    for (int t = 0; t < T_; t++) {
        if (tid < 512) {
            const float* hb = g_hT + ((size_t)t * 4 + g) * 4096;
            {
                int off = (w * 32 + (lane >> 1)) * 8 + (lane & 1) * 4;
                float4 v0 = __ldcg((const float4*)(hb + off));
                float4 v1 = __ldcg((const float4*)(hb + off + 128));
                *(float4*)(hs + off) = v0;
                *(float4*)(hs + off + 128) = v1;
            }
            __syncwarp();

            ull acc[4][4];
#pragma unroll
            for (int u = 0; u < 4; u++)
#pragma unroll
                for (int c = 0; c < 4; c++) acc[u][c] = 0ULL;

#pragma unroll
            for (int i = 0; i < 16; i++) {
                int k = kbase + i;
                ulonglong2 hA = *(const ulonglong2*)(hs + k * 8);
                ulonglong2 hB = *(const ulonglong2*)(hs + k * 8 + 4);
                ull hv[4] = {hA.x, hA.y, hB.x, hB.y};
                float4 wf = *(const float4*)(ws + k * 64 + cg4);
                ull wb[4] = {bcast2(wf.x), bcast2(wf.y), bcast2(wf.z), bcast2(wf.w)};
#pragma unroll
                for (int u = 0; u < 4; u++)
#pragma unroll
                    for (int c = 0; c < 4; c++)
                        fma2(acc[u][c], hv[u], wb[c]);
            }
#pragma unroll
            for (int u = 0; u < 4; u++)
#pragma unroll
                for (int c = 0; c < 4; c++) {
                    ull o = __shfl_xor_sync(0xFFFFFFFFu, acc[u][c], 16);
                    add2(acc[u][c], o);
                }
            if (kg == 0) {
                ull* pl = ap + w * APW;
#pragma unroll
                for (int u = 0; u < 4; u++) {
                    ulonglong2 s0, s1;
                    s0.x = acc[u][0]; s0.y = acc[u][1];
                    s1.x = acc[u][2]; s1.y = acc[u][3];
                    *(ulonglong2*)(pl + u * 72 + cg4)     = s0;
                    *(ulonglong2*)(pl + u * 72 + cg4 + 2) = s1;
                }
            }
            __syncthreads();
            __syncthreads();
        } else {
            __syncthreads();

            ull s0 = 0ULL, s1 = 0ULL, s2 = 0ULL, s3 = 0ULL;
            const ull* base = ap + np * 72 + jc;
#pragma unroll
            for (int p = 0; p < 16; p++) {
                const ull* pl = base + p * APW;
                add2(s0, pl[0]);
                add2(s1, pl[16]);
                add2(s2, pl[32]);
                add2(s3, pl[48]);
            }
            float a0l, a0h, a1l, a1h, a2l, a2h, a3l, a3h;
            unpack2(a0l, a0h, s0);
            unpack2(a1l, a1h, s1);
            unpack2(a2l, a2h, s2);
            unpack2(a3l, a3h, s3);

            float ig0 = fsig(a0l + xwr[0][0]);
            float fg0 = fsig(a1l + xwr[0][1]);
            float og0 = fsig(a2l + xwr[0][2]);
            float gg0 = ftanh(a3l + xwr[0][3]);
            c0v = fg0 * c0v + ig0 * gg0;
            float hn0 = og0 * ftanh(c0v);

            float ig1 = fsig(a0h + xwr[1][0]);
            float fg1 = fsig(a1h + xwr[1][1]);
            float og1 = fsig(a2h + xwr[1][2]);
            float gg1 = ftanh(a3h + xwr[1][3]);
            c1v = fg1 * c1v + ig1 * gg1;
            float hn1 = og1 * ftanh(c1v);

            float2 hv2; hv2.x = hn0; hv2.y = hn1;
            *(float2*)(g_hT + ((size_t)(t + 1) * 4 + g) * 4096 + (r * 16 + jc) * 8 + 2 * np) = hv2;

            if (t + 1 < T_) {
                const float* xb = g_xw2 + ((size_t)(t + 1) * NB + b) * 512;
#pragma unroll
                for (int rr = 0; rr < 2; rr++)
#pragma unroll
                    for (int q = 0; q < 4; q++)
                        xwr[rr][q] = __ldcg(xb + (2 * np + rr) * 64 + q * 16 + jc);
            }
            __syncthreads();
        }
        gridbar(g, r, step); step++;
    }
}

// ---------------- T2: g_hT[t+1][g][j][n8] -> out[n][t][j] --------------------------
__global__ __launch_bounds__(512) void out_transpose_kernel(float* __restrict__ out)
{
    extern __shared__ float sm[];
    const int t = blockIdx.x;
    const int tid = threadIdx.x;
    const float* src = g_hT + (size_t)(t + 1) * 4 * 4096;
#pragma unroll
    for (int it = 0; it < 8; it++) {
        int idx = tid + it * 512;
        *(float4*)(sm + idx * 4) = __ldcg((const float4*)(src + idx * 4));
    }
    __syncthreads();
    const int n = tid >> 4, jb = (tid & 15) * 32;
    const int gbase = (n >> 3) * 4096, n8 = n & 7;
#pragma unroll
    for (int it = 0; it < 8; it++) {
        int j = jb + it * 4;
        float4 v;
        v.x = sm[gbase + (j + 0) * 8 + n8];
        v.y = sm[gbase + (j + 1) * 8 + n8];
        v.z = sm[gbase + (j + 2) * 8 + n8];
        v.w = sm[gbase + (j + 3) * 8 + n8];
        *(float4*)(out + ((size_t)n * T_ + t) * H_ + j) = v;
    }
}

// ---------------- launch ----------------------------------------------------------
extern "C" void kernel_launch(void* const* d_in, const int* in_sizes, int n_in,
                              void* d_out, int out_size)
{
    const float* x    = (const float*)d_in[0];
    const float* h0   = (const float*)d_in[1];
    const float* Wx   = (const float*)d_in[2];
    const float* Wh   = (const float*)d_in[3];
    const float* bias = (const float*)d_in[4];
    float* out = (float*)d_out;

    init_state_kernel<<<64, 256>>>(h0);

    const int sh1 = (2 * AS_BUF + 2 * BS_BUF) * (int)sizeof(float);
    cudaFuncSetAttribute(gemm_xw_tc, cudaFuncAttributeMaxDynamicSharedMemorySize, sh1);
    dim3 g1(G4 / 128, (N_ * T_) / 128);
    gemm_xw_tc<<<g1, 256, sh1>>>(x, Wx, bias);

    dim3 gt1(T_, 4);
    xw_transpose_kernel<<<gt1, 512>>>();

    const int shmem = (512 * 64 + 512 * 8) * 4 + 16 * APW * 8;
    cudaFuncSetAttribute(lstm_rec_kernel, cudaFuncAttributeMaxDynamicSharedMemorySize, shmem);
    lstm_rec_kernel<<<NB, NTH, shmem>>>(Wh);

    cudaFuncSetAttribute(out_transpose_kernel, cudaFuncAttributeMaxDynamicSharedMemorySize, 65536);
    out_transpose_kernel<<<T_, 512, 65536>>>(out);
}

// round 12
// speedup vs baseline: 2.5109x; 1.0952x over previous
#include <cuda_runtime.h>
#include <cstdint>
#include <math.h>

#define N_  32
#define T_  1024
#define D_  512
#define H_  512
#define G4  2048

#define NB   128
#define NTH  576    // 16 GEMM warps + 2 reduce warps
#define APW  288    // partial plane stride (ull): 4 np * 72

typedef unsigned long long ull;

__device__ __forceinline__ void fma2(ull& d, const ull a, const ull b) {
    asm("fma.rn.f32x2 %0, %1, %2, %0;" : "+l"(d) : "l"(a), "l"(b));
}
__device__ __forceinline__ void add2(ull& d, const ull a) {
    asm("add.rn.f32x2 %0, %0, %1;" : "+l"(d) : "l"(a));
}
__device__ __forceinline__ ull bcast2(float x) {
    ull r; asm("mov.b64 %0, {%1, %1};" : "=l"(r) : "f"(x)); return r;
}
__device__ __forceinline__ void unpack2(float& lo, float& hi, ull a) {
    asm("mov.b64 {%0, %1}, %2;" : "=f"(lo), "=f"(hi) : "l"(a));
}
__device__ __forceinline__ float fsig(float x) { return 1.f / (1.f + __expf(-x)); }
__device__ __forceinline__ float ftanh(float x) { return 2.f / (1.f + __expf(-2.f * x)) - 1.f; }

// ---- cp.async helpers ----
__device__ __forceinline__ void cp_async16(void* dst, const void* src) {
    unsigned s = (unsigned)__cvta_generic_to_shared(dst);
    asm volatile("cp.async.cg.shared.global [%0], [%1], 16;" :: "r"(s), "l"(src));
}
__device__ __forceinline__ void cp_commit() {
    asm volatile("cp.async.commit_group;" ::: "memory");
}
template <int NN> __device__ __forceinline__ void cp_wait() {
    asm volatile("cp.async.wait_group %0;" :: "n"(NN) : "memory");
}

// ---- tf32 mma helpers ----
__device__ __forceinline__ uint32_t f2tf(float x) {
    uint32_t r; asm("cvt.rna.tf32.f32 %0, %1;" : "=r"(r) : "f"(x)); return r;
}
__device__ __forceinline__ void mma_tf32(float* c, const uint32_t* a, const uint32_t* b) {
    asm("mma.sync.aligned.m16n8k8.row.col.f32.tf32.tf32.f32 "
        "{%0,%1,%2,%3},{%4,%5,%6,%7},{%8,%9},{%0,%1,%2,%3};"
        : "+f"(c[0]), "+f"(c[1]), "+f"(c[2]), "+f"(c[3])
        : "r"(a[0]), "r"(a[1]), "r"(a[2]), "r"(a[3]), "r"(b[0]), "r"(b[1]));
}

// ---------------- device scratch -------------------------------------------------
__device__ float g_xw [(size_t)N_ * T_ * G4];          // phase1 out: [n][t][2048]
__device__ float g_xw2[(size_t)T_ * NB * 512];         // [t][cta][n8][gate][j16]
__device__ float g_hT [(size_t)(T_ + 1) * 4 * 4096];   // h history: [t][g][k(512)][n8(8)]
__device__ unsigned int g_cnt[4 * 64];                 // per-group step counters (monotonic)

// ---------------- init: counters + h0 -> g_hT[0] ----------------------------------
__global__ void init_state_kernel(const float* __restrict__ h0)
{
    int i = blockIdx.x * blockDim.x + threadIdx.x;
    if (i < 4) g_cnt[i * 64] = 0u;
    if (i < 4 * 512 * 8) {
        int g = i >> 12, k = (i >> 3) & 511, n8 = i & 7;
        g_hT[(size_t)g * 4096 + k * 8 + n8] = h0[(size_t)(g * 8 + n8) * H_ + k];
    }
}

// ---------------- Phase 1: xw = x @ Wx + b  via tf32 tensor cores ------------------
#define AS_STR 40
#define BS_STR 132
#define AS_BUF (128 * AS_STR)
#define BS_BUF (32 * BS_STR)

__global__ __launch_bounds__(256) void gemm_xw_tc(const float* __restrict__ x,
                                                  const float* __restrict__ Wx,
                                                  const float* __restrict__ bias)
{
    extern __shared__ float sm1[];
    float* As = sm1;
    float* Bs = sm1 + 2 * AS_BUF;

    const int tid  = threadIdx.x;
    const int bn   = blockIdx.x, bm = blockIdx.y;
    const int warp = tid >> 5, lane = tid & 31;
    const int wy = warp & 1, wx = warp >> 1;
    const int g  = lane >> 2, tg = lane & 3;

    float acc[4][4][4];
#pragma unroll
    for (int mi = 0; mi < 4; mi++)
#pragma unroll
        for (int ni = 0; ni < 4; ni++)
#pragma unroll
            for (int c = 0; c < 4; c++) acc[mi][ni][c] = 0.f;

    {
#pragma unroll
        for (int i = 0; i < 4; i++) {
            int flat = i * 256 + tid;
            int m = flat >> 3, kc = flat & 7;
            cp_async16(As + m * AS_STR + kc * 4,
                       x + (size_t)(bm * 128 + m) * D_ + kc * 4);
        }
#pragma unroll
        for (int i = 0; i < 4; i++) {
            int flat = i * 256 + tid;
            int k = flat >> 5, nc = flat & 31;
            cp_async16(Bs + k * BS_STR + nc * 4,
                       Wx + (size_t)k * G4 + bn * 128 + nc * 4);
        }
        cp_commit();
    }

    for (int it = 0; it < 16; it++) {
        if (it < 15) {
            const int k0 = (it + 1) * 32;
            const int nb = (it + 1) & 1;
#pragma unroll
            for (int i = 0; i < 4; i++) {
                int flat = i * 256 + tid;
                int m = flat >> 3, kc = flat & 7;
                cp_async16(As + nb * AS_BUF + m * AS_STR + kc * 4,
                           x + (size_t)(bm * 128 + m) * D_ + k0 + kc * 4);
            }
#pragma unroll
            for (int i = 0; i < 4; i++) {
                int flat = i * 256 + tid;
                int k = flat >> 5, nc = flat & 31;
                cp_async16(Bs + nb * BS_BUF + k * BS_STR + nc * 4,
                           Wx + (size_t)(k0 + k) * G4 + bn * 128 + nc * 4);
            }
            cp_commit();
            cp_wait<1>();
        } else {
            cp_wait<0>();
        }
        __syncthreads();

        const float* Ab = As + (it & 1) * AS_BUF;
        const float* Bb = Bs + (it & 1) * BS_BUF;
#pragma unroll
        for (int ks = 0; ks < 4; ks++) {
            uint32_t af[4][4], bf[4][2];
#pragma unroll
            for (int mi = 0; mi < 4; mi++) {
                const float* ap_ = Ab + (wy * 64 + mi * 16) * AS_STR + ks * 8;
                af[mi][0] = f2tf(ap_[ g      * AS_STR + tg    ]);
                af[mi][1] = f2tf(ap_[(g + 8) * AS_STR + tg    ]);
                af[mi][2] = f2tf(ap_[ g      * AS_STR + tg + 4]);
                af[mi][3] = f2tf(ap_[(g + 8) * AS_STR + tg + 4]);
            }
#pragma unroll
            for (int ni = 0; ni < 4; ni++) {
                const float* bp_ = Bb + ks * 8 * BS_STR + wx * 32 + ni * 8 + g;
                bf[ni][0] = f2tf(bp_[ tg      * BS_STR]);
                bf[ni][1] = f2tf(bp_[(tg + 4) * BS_STR]);
            }
#pragma unroll
            for (int mi = 0; mi < 4; mi++)
#pragma unroll
                for (int ni = 0; ni < 4; ni++)
                    mma_tf32(acc[mi][ni], af[mi], bf[ni]);
        }
        __syncthreads();
    }

#pragma unroll
    for (int ni = 0; ni < 4; ni++) {
        int col = bn * 128 + wx * 32 + ni * 8 + 2 * tg;
        float b0 = bias[col], b1 = bias[col + 1];
#pragma unroll
        for (int mi = 0; mi < 4; mi++) {
            int row0 = bm * 128 + wy * 64 + mi * 16 + g;
            float2 v0; v0.x = acc[mi][ni][0] + b0; v0.y = acc[mi][ni][1] + b1;
            float2 v1; v1.x = acc[mi][ni][2] + b0; v1.y = acc[mi][ni][3] + b1;
            *(float2*)(g_xw + (size_t)row0 * G4 + col)       = v0;
            *(float2*)(g_xw + (size_t)(row0 + 8) * G4 + col) = v1;
        }
    }
}

// ---------------- T1: g_xw[n][t][2048] -> g_xw2[t][cta][n8][gate][j16] -------------
__global__ __launch_bounds__(512) void xw_transpose_kernel()
{
    const int t = blockIdx.x;
    const int g = blockIdx.y;
#pragma unroll
    for (int it = 0; it < 8; it++) {
        int flat = it * 512 + threadIdx.x;
        int r    = flat >> 7;
        int n8   = (flat >> 4) & 7;
        int gate = (flat >> 2) & 3;
        int jl4  = flat & 3;
        float4 v = __ldcg((const float4*)(g_xw +
                    ((size_t)(g * 8 + n8) * T_ + t) * G4 + gate * 512 + r * 16 + jl4 * 4));
        *(float4*)(g_xw2 + (((size_t)t * NB + g * 32 + r) * 8 + n8) * 64
                         + gate * 16 + jl4 * 4) = v;
    }
}

// ---------------- Phase 2: per-group persistent, producer-signal sync --------------
extern __shared__ float smem_dyn[];

__global__ __launch_bounds__(NTH, 1) void lstm_rec_kernel(const float* __restrict__ Wh)
{
    float* ws = smem_dyn;                       // [512][64]
    float* hs = ws + 512 * 64;                  // [512][8]
    ull*   ap = (ull*)(hs + 512 * 8);           // [16][APW]

    const int b   = blockIdx.x;
    const int g   = b >> 5;          // group 0..3 (batch n = g*8..g*8+7)
    const int r   = b & 31;          // rank: j-columns [r*16, r*16+16)
    const int tid = threadIdx.x;

    for (int idx = tid; idx < 512 * 64; idx += NTH) {
        int k = idx >> 6, c = idx & 63;
        ws[idx] = Wh[(size_t)k * G4 + (c >> 4) * 512 + r * 16 + (c & 15)];
    }
    __syncthreads();

    unsigned* cntp = &g_cnt[g * 64];

    if (tid < 512) {
        // ================= GEMM worker warps =================
        const int w    = tid >> 5;
        const int lane = tid & 31;
        const int kg   = lane >> 4;
        const int pos  = lane & 15;
        const int cg4  = pos * 4;
        const int kbase = w * 32 + kg * 16;

        for (int t = 0; t < T_; t++) {
            if (t > 0) {
                unsigned target = 32u * (unsigned)t, v;
                do {
                    asm volatile("ld.acquire.gpu.global.u32 %0, [%1];"
                                 : "=r"(v) : "l"(cntp) : "memory");
                } while (v < target);
            }
            // stage own k-slice of h (two float4 per lane)
            const float* hb = g_hT + ((size_t)t * 4 + g) * 4096;
            {
                int off = (w * 32 + (lane >> 1)) * 8 + (lane & 1) * 4;
                float4 v0 = __ldcg((const float4*)(hb + off));
                float4 v1 = __ldcg((const float4*)(hb + off + 128));
                *(float4*)(hs + off) = v0;
                *(float4*)(hs + off + 128) = v1;
            }
            __syncwarp();

            ull acc[4][4];
#pragma unroll
            for (int u = 0; u < 4; u++)
#pragma unroll
                for (int c = 0; c < 4; c++) acc[u][c] = 0ULL;

#pragma unroll
            for (int i = 0; i < 16; i++) {
                int k = kbase + i;
                ulonglong2 hA = *(const ulonglong2*)(hs + k * 8);
                ulonglong2 hB = *(const ulonglong2*)(hs + k * 8 + 4);
                ull hv[4] = {hA.x, hA.y, hB.x, hB.y};
                float4 wf = *(const float4*)(ws + k * 64 + cg4);
                ull wb[4] = {bcast2(wf.x), bcast2(wf.y), bcast2(wf.z), bcast2(wf.w)};
#pragma unroll
                for (int u = 0; u < 4; u++)
#pragma unroll
                    for (int c = 0; c < 4; c++)
                        fma2(acc[u][c], hv[u], wb[c]);
            }
#pragma unroll
            for (int u = 0; u < 4; u++)
#pragma unroll
                for (int c = 0; c < 4; c++) {
                    ull o = __shfl_xor_sync(0xFFFFFFFFu, acc[u][c], 16);
                    add2(acc[u][c], o);
                }
            if (kg == 0) {
                ull* pl = ap + w * APW;
#pragma unroll
                for (int u = 0; u < 4; u++) {
                    ulonglong2 s0, s1;
                    s0.x = acc[u][0]; s0.y = acc[u][1];
                    s1.x = acc[u][2]; s1.y = acc[u][3];
                    *(ulonglong2*)(pl + u * 72 + cg4)     = s0;
                    *(ulonglong2*)(pl + u * 72 + cg4 + 2) = s1;
                }
            }
            asm volatile("membar.cta;");
            asm volatile("bar.arrive 1, %0;" :: "n"(NTH));
        }
    } else {
        // ================= reduce / gates warps (tid 512..575) =================
        const int rt = tid - 512;
        const int np = rt >> 4, jc = rt & 15;

        float c0v = 0.f, c1v = 0.f;
        float xwr[2][4];
        {
            const float* xb = g_xw2 + (size_t)b * 512;
#pragma unroll
            for (int rr = 0; rr < 2; rr++)
#pragma unroll
                for (int q = 0; q < 4; q++)
                    xwr[rr][q] = __ldcg(xb + (2 * np + rr) * 64 + q * 16 + jc);
        }

        for (int t = 0; t < T_; t++) {
            asm volatile("bar.sync 1, %0;" :: "n"(NTH));

            ull s0 = 0ULL, s1 = 0ULL, s2 = 0ULL, s3 = 0ULL;
            const ull* base = ap + np * 72 + jc;
#pragma unroll
            for (int p = 0; p < 16; p++) {
                const ull* pl = base + p * APW;
                add2(s0, pl[0]);
                add2(s1, pl[16]);
                add2(s2, pl[32]);
                add2(s3, pl[48]);
            }
            float a0l, a0h, a1l, a1h, a2l, a2h, a3l, a3h;
            unpack2(a0l, a0h, s0);
            unpack2(a1l, a1h, s1);
            unpack2(a2l, a2h, s2);
            unpack2(a3l, a3h, s3);

            float ig0 = fsig(a0l + xwr[0][0]);
            float fg0 = fsig(a1l + xwr[0][1]);
            float og0 = fsig(a2l + xwr[0][2]);
            float gg0 = ftanh(a3l + xwr[0][3]);
            c0v = fg0 * c0v + ig0 * gg0;
            float hn0 = og0 * ftanh(c0v);

            float ig1 = fsig(a0h + xwr[1][0]);
            float fg1 = fsig(a1h + xwr[1][1]);
            float og1 = fsig(a2h + xwr[1][2]);
            float gg1 = ftanh(a3h + xwr[1][3]);
            c1v = fg1 * c1v + ig1 * gg1;
            float hn1 = og1 * ftanh(c1v);

            // publish h(t+1) straight to L2
            {
                float2 hv2; hv2.x = hn0; hv2.y = hn1;
                float* dst = g_hT + ((size_t)(t + 1) * 4 + g) * 4096 + (r * 16 + jc) * 8 + 2 * np;
                asm volatile("st.global.cg.v2.f32 [%0], {%1, %2};"
                             :: "l"(dst), "f"(hv2.x), "f"(hv2.y) : "memory");
            }
            asm volatile("bar.sync 2, 64;");
            if (rt == 0) {
                __threadfence();
                atomicAdd(cntp, 1u);
            }
            // off critical path: next xw prefetch
            if (t + 1 < T_) {
                const float* xb = g_xw2 + ((size_t)(t + 1) * NB + b) * 512;
#pragma unroll
                for (int rr = 0; rr < 2; rr++)
#pragma unroll
                    for (int q = 0; q < 4; q++)
                        xwr[rr][q] = __ldcg(xb + (2 * np + rr) * 64 + q * 16 + jc);
            }
        }
    }
}

// ---------------- T2: g_hT[t+1][g][j][n8] -> out[n][t][j] --------------------------
__global__ __launch_bounds__(512) void out_transpose_kernel(float* __restrict__ out)
{
    extern __shared__ float sm[];
    const int t = blockIdx.x;
    const int tid = threadIdx.x;
    const float* src = g_hT + (size_t)(t + 1) * 4 * 4096;
#pragma unroll
    for (int it = 0; it < 8; it++) {
        int idx = tid + it * 512;
        *(float4*)(sm + idx * 4) = __ldcg((const float4*)(src + idx * 4));
    }
    __syncthreads();
    const int n = tid >> 4, jb = (tid & 15) * 32;
    const int gbase = (n >> 3) * 4096, n8 = n & 7;
#pragma unroll
    for (int it = 0; it < 8; it++) {
        int j = jb + it * 4;
        float4 v;
        v.x = sm[gbase + (j + 0) * 8 + n8];
        v.y = sm[gbase + (j + 1) * 8 + n8];
        v.z = sm[gbase + (j + 2) * 8 + n8];
        v.w = sm[gbase + (j + 3) * 8 + n8];
        *(float4*)(out + ((size_t)n * T_ + t) * H_ + j) = v;
    }
}

// ---------------- launch ----------------------------------------------------------
extern "C" void kernel_launch(void* const* d_in, const int* in_sizes, int n_in,
                              void* d_out, int out_size)
{
    const float* x    = (const float*)d_in[0];
    const float* h0   = (const float*)d_in[1];
    const float* Wx   = (const float*)d_in[2];
    const float* Wh   = (const float*)d_in[3];
    const float* bias = (const float*)d_in[4];
    float* out = (float*)d_out;

    init_state_kernel<<<64, 256>>>(h0);

    const int sh1 = (2 * AS_BUF + 2 * BS_BUF) * (int)sizeof(float);
    cudaFuncSetAttribute(gemm_xw_tc, cudaFuncAttributeMaxDynamicSharedMemorySize, sh1);
    dim3 g1(G4 / 128, (N_ * T_) / 128);
    gemm_xw_tc<<<g1, 256, sh1>>>(x, Wx, bias);

    dim3 gt1(T_, 4);
    xw_transpose_kernel<<<gt1, 512>>>();

    const int shmem = (512 * 64 + 512 * 8) * 4 + 16 * APW * 8;
    cudaFuncSetAttribute(lstm_rec_kernel, cudaFuncAttributeMaxDynamicSharedMemorySize, shmem);
    lstm_rec_kernel<<<NB, NTH, shmem>>>(Wh);

    cudaFuncSetAttribute(out_transpose_kernel, cudaFuncAttributeMaxDynamicSharedMemorySize, 65536);
    out_transpose_kernel<<<T_, 512, 65536>>>(out);
}